// round 7
// baseline (speedup 1.0000x reference)
#include <cuda_runtime.h>
#include <cuda_bf16.h>
#include <mma.h>
#include <cstdint>

using namespace nvcuda;

// Problem constants
#define B_  2
#define S_  2048
#define E_  1024
#define NH_ 16
#define NKV_ 4
#define HD_ 64
#define GS_ 4
#define MTOT (B_*S_)    // 4096

// ---------------- scratch (no cudaMalloc allowed) ----------------
// f32 GEMM outputs
__device__ __align__(16) float g_q[MTOT * 1024];
__device__ __align__(16) float g_k[MTOT * 256];
__device__ __align__(16) float g_v[MTOT * 256];
// bf16 hi/lo splits of GEMM inputs
__device__ __align__(16) __nv_bfloat16 g_qxh[MTOT*1024], g_qxl[MTOT*1024];
__device__ __align__(16) __nv_bfloat16 g_kxh[MTOT*1024], g_kxl[MTOT*1024];
__device__ __align__(16) __nv_bfloat16 g_vxh[MTOT*1024], g_vxl[MTOT*1024];
__device__ __align__(16) __nv_bfloat16 g_wqh[1024*1024], g_wql[1024*1024];
__device__ __align__(16) __nv_bfloat16 g_wkh[256*1024],  g_wkl[256*1024];
__device__ __align__(16) __nv_bfloat16 g_wvh[256*1024],  g_wvl[256*1024];
__device__ __align__(16) __nv_bfloat16 g_woh[1024*1024], g_wol[1024*1024];
// attention operands (pre-split bf16)
__device__ __align__(16) __nv_bfloat16 g_qah[MTOT*1024], g_qal[MTOT*1024];     // Q scaled [b][s][h*64+d]
__device__ __align__(16) __nv_bfloat16 g_kah[B_*NKV_*S_*HD_], g_kal[B_*NKV_*S_*HD_]; // [b][kvh][s][d]
__device__ __align__(16) __nv_bfloat16 g_vth[B_*NKV_*S_*HD_], g_vtl[B_*NKV_*S_*HD_]; // [b][kvh][d][s]
// attention output (pre-split for O GEMM)
__device__ __align__(16) __nv_bfloat16 g_ah[MTOT*1024], g_al[MTOT*1024];

// ---------------- helpers ----------------
__device__ __forceinline__ uint32_t pack2(float x, float y) {
    __nv_bfloat162 t = __floats2bfloat162_rn(x, y);
    return *(uint32_t*)&t;
}
__device__ __forceinline__ float bf16hi(float x) {
    return __bfloat162float(__float2bfloat16_rn(x));
}
__device__ __forceinline__ void split2(float2 v, uint32_t& hi, uint32_t& lo) {
    float hx = bf16hi(v.x), hy = bf16hi(v.y);
    hi = pack2(hx, hy);
    lo = pack2(v.x - hx, v.y - hy);
}
__device__ __forceinline__ void mma_bf16(float c[4], const uint32_t a[4],
                                         uint32_t b0, uint32_t b1)
{
    asm volatile(
        "mma.sync.aligned.m16n8k16.row.col.f32.bf16.bf16.f32 "
        "{%0,%1,%2,%3}, {%4,%5,%6,%7}, {%8,%9}, {%0,%1,%2,%3};"
        : "+f"(c[0]), "+f"(c[1]), "+f"(c[2]), "+f"(c[3])
        : "r"(a[0]), "r"(a[1]), "r"(a[2]), "r"(a[3]), "r"(b0), "r"(b1));
}
__device__ __forceinline__ void cp16(void* smem_dst, const void* gsrc) {
    uint32_t d = (uint32_t)__cvta_generic_to_shared(smem_dst);
    asm volatile("cp.async.ca.shared.global [%0], [%1], 16;" :: "r"(d), "l"(gsrc));
}

// ---------------- elementwise split: f32 -> bf16 hi/lo ----------------
__global__ void split_kernel(const float4* __restrict__ in,
                             uint2* __restrict__ hi, uint2* __restrict__ lo, int n4)
{
    int i = blockIdx.x * blockDim.x + threadIdx.x;
    if (i >= n4) return;
    float4 v = in[i];
    uint32_t h0, l0, h1, l1;
    split2(make_float2(v.x, v.y), h0, l0);
    split2(make_float2(v.z, v.w), h1, l1);
    hi[i] = make_uint2(h0, h1);
    lo[i] = make_uint2(l0, l1);
}

// Q for attention: scale by 0.125 then split (same layout)
__global__ void conv_q_kernel(const float4* __restrict__ in,
                              uint2* __restrict__ hi, uint2* __restrict__ lo, int n4)
{
    int i = blockIdx.x * blockDim.x + threadIdx.x;
    if (i >= n4) return;
    float4 v = in[i];
    v.x *= 0.125f; v.y *= 0.125f; v.z *= 0.125f; v.w *= 0.125f;
    uint32_t h0, l0, h1, l1;
    split2(make_float2(v.x, v.y), h0, l0);
    split2(make_float2(v.z, v.w), h1, l1);
    hi[i] = make_uint2(h0, h1);
    lo[i] = make_uint2(l0, l1);
}

// K: [b][s][kvh*64+d] f32 -> [b][kvh][s][d] bf16 hi/lo
__global__ void conv_k_kernel(const float4* __restrict__ in,
                              uint2* __restrict__ hi, uint2* __restrict__ lo)
{
    int i = blockIdx.x * blockDim.x + threadIdx.x;  // over MTOT*256/4 = 262144
    int c4 = i & 63;
    int s  = (i >> 6) & 2047;
    int b  = i >> 17;
    int kvh = c4 >> 4, d4 = c4 & 15;
    float4 v = in[i];
    uint32_t h0, l0, h1, l1;
    split2(make_float2(v.x, v.y), h0, l0);
    split2(make_float2(v.z, v.w), h1, l1);
    int o = ((b * 4 + kvh) * 2048 + s) * 16 + d4;
    hi[o] = make_uint2(h0, h1);
    lo[o] = make_uint2(l0, l1);
}

// V: [b][s][kvh*64+d] f32 -> transposed [b][kvh][d][s] bf16 hi/lo
__global__ void conv_vt_kernel(const float* __restrict__ V,
                               __nv_bfloat16* __restrict__ vth,
                               __nv_bfloat16* __restrict__ vtl)
{
    __shared__ float ts[32][33];
    const int s0 = blockIdx.x * 32, d0 = blockIdx.y * 32;
    const int bh = blockIdx.z;                 // b*4+kvh
    const int b = bh >> 2, kvh = bh & 3;
    const int x = threadIdx.x, y = threadIdx.y;

    #pragma unroll
    for (int l = 0; l < 4; l++) {
        int s = s0 + y + l * 8;
        ts[y + l * 8][x] = V[((size_t)(b * 2048 + s)) * 256 + kvh * 64 + d0 + x];
    }
    __syncthreads();
    #pragma unroll
    for (int l = 0; l < 4; l++) {
        int d = d0 + y + l * 8;
        float f = ts[x][y + l * 8];
        float h = bf16hi(f);
        size_t o = ((size_t)(bh * 64 + d)) * 2048 + s0 + x;
        vth[o] = __float2bfloat16_rn(h);
        vtl[o] = __float2bfloat16_rn(f - h);
    }
}

// ---------------------------------------------------------------------------
// bf16 hi/lo split GEMM: C[M,N] = A[M,K] @ B[N,K]^T, fp32 accum.
// Block 128x128, BK=16, 2-stage cp.async, 8 warps (warp 64x32), wmma 16x16x16.
// C = Ah*Bl + Al*Bh + Ah*Bh  (error ~2^-16)
// ---------------------------------------------------------------------------
#define GST 24   // bf16 row stride in smem (48B -> conflict-free LDSM)

__global__ __launch_bounds__(256, 2)
void gemm_bf16_kernel(const __nv_bfloat16* __restrict__ Ah, const __nv_bfloat16* __restrict__ Al,
                      const __nv_bfloat16* __restrict__ Bh, const __nv_bfloat16* __restrict__ Bl,
                      float* __restrict__ C, int M, int N, int K)
{
    __shared__ __nv_bfloat16 Xs[2][2][128][GST];   // [stage][hi/lo]
    __shared__ __nv_bfloat16 Ws[2][2][128][GST];

    const int tid = threadIdx.x;
    const int wid = tid >> 5;
    const int wr  = wid & 1;
    const int wc  = wid >> 1;
    const int m0  = blockIdx.y * 128;
    const int n0  = blockIdx.x * 128;

    wmma::fragment<wmma::accumulator, 16, 16, 16, float> acc[4][2];
    #pragma unroll
    for (int i = 0; i < 4; i++)
        #pragma unroll
        for (int j = 0; j < 2; j++)
            wmma::fill_fragment(acc[i][j], 0.0f);

    auto prefetch = [&](int kt, int st) {
        const int k0 = kt * 16;
        #pragma unroll
        for (int l = 0; l < 4; l++) {
            int idx = tid + l * 256;            // 0..1023
            int c   = idx & 1;
            int r   = (idx >> 1) & 127;
            int hl  = (idx >> 8) & 1;
            int xw  = idx >> 9;
            if (xw == 0) {
                const __nv_bfloat16* s = (hl ? Al : Ah) + (size_t)(m0 + r) * K + k0 + c * 8;
                cp16(&Xs[st][hl][r][c * 8], s);
            } else {
                const __nv_bfloat16* s = (hl ? Bl : Bh) + (size_t)(n0 + r) * K + k0 + c * 8;
                cp16(&Ws[st][hl][r][c * 8], s);
            }
        }
        asm volatile("cp.async.commit_group;");
    };

    const int nKT = K / 16;
    prefetch(0, 0);

    for (int kt = 0; kt < nKT; kt++) {
        asm volatile("cp.async.wait_group 0;");
        __syncthreads();
        if (kt + 1 < nKT) prefetch(kt + 1, (kt + 1) & 1);
        const int st = kt & 1;

        wmma::fragment<wmma::matrix_a, 16, 16, 16, __nv_bfloat16, wmma::row_major> fah[4], fal[4];
        wmma::fragment<wmma::matrix_b, 16, 16, 16, __nv_bfloat16, wmma::col_major> fbh[2], fbl[2];
        #pragma unroll
        for (int i = 0; i < 4; i++) {
            wmma::load_matrix_sync(fah[i], &Xs[st][0][wr * 64 + i * 16][0], GST);
            wmma::load_matrix_sync(fal[i], &Xs[st][1][wr * 64 + i * 16][0], GST);
        }
        #pragma unroll
        for (int j = 0; j < 2; j++) {
            wmma::load_matrix_sync(fbh[j], &Ws[st][0][wc * 32 + j * 16][0], GST);
            wmma::load_matrix_sync(fbl[j], &Ws[st][1][wc * 32 + j * 16][0], GST);
        }
        #pragma unroll
        for (int i = 0; i < 4; i++)
            #pragma unroll
            for (int j = 0; j < 2; j++) {
                wmma::mma_sync(acc[i][j], fah[i], fbl[j], acc[i][j]);
                wmma::mma_sync(acc[i][j], fal[i], fbh[j], acc[i][j]);
                wmma::mma_sync(acc[i][j], fah[i], fbh[j], acc[i][j]);
            }
    }

    #pragma unroll
    for (int i = 0; i < 4; i++)
        #pragma unroll
        for (int j = 0; j < 2; j++)
            wmma::store_matrix_sync(&C[(size_t)(m0 + wr * 64 + i * 16) * N + n0 + wc * 32 + j * 16],
                                    acc[i][j], N, wmma::mem_row_major);
}

// ---------------------------------------------------------------------------
// Flash attention, bf16 hi/lo split mma.m16n8k16, pre-converted operands.
// CTA 128 thr / 4 warps, BQ=64, BK=32. P built by register repack (no smem).
// Emits attn output as bf16 hi/lo for the O-projection GEMM.
// ---------------------------------------------------------------------------
#define ABQ 64
#define ABK 32

__global__ __launch_bounds__(128, 4)
void attn_mma_kernel(const uint32_t* __restrict__ qh, const uint32_t* __restrict__ ql,
                     const __nv_bfloat16* __restrict__ kh, const __nv_bfloat16* __restrict__ kl,
                     const __nv_bfloat16* __restrict__ vth, const __nv_bfloat16* __restrict__ vtl,
                     uint32_t* __restrict__ oh, uint32_t* __restrict__ ol)
{
    __shared__ __align__(16) uint32_t sK[2][32 * 36];   // [hi/lo][key][d-pair], stride 36
    __shared__ __align__(16) uint32_t sV[2][64 * 20];   // [hi/lo][d][key-pair], stride 20

    const int qb   = gridDim.x - 1 - blockIdx.x;
    const int h    = blockIdx.y;
    const int b    = blockIdx.z;
    const int kvh  = h >> 2;
    const int tid  = threadIdx.x;
    const int lane = tid & 31;
    const int w    = tid >> 5;
    const int g    = lane >> 2;
    const int tig  = lane & 3;

    const int r0g = qb * ABQ + w * 16 + g;
    const int r1g = r0g + 8;

    // ---- Q A-fragments straight from global (one-time) ----
    uint32_t qhi[4][4], qlo[4][4];
    {
        const size_t b0 = (((size_t)(b * S_ + r0g)) * 1024 + h * 64) >> 1;
        const size_t b1 = (((size_t)(b * S_ + r1g)) * 1024 + h * 64) >> 1;
        #pragma unroll
        for (int kc = 0; kc < 4; kc++) {
            int c0 = kc * 8 + tig, c1 = c0 + 4;
            qhi[kc][0] = qh[b0 + c0]; qhi[kc][1] = qh[b1 + c0];
            qhi[kc][2] = qh[b0 + c1]; qhi[kc][3] = qh[b1 + c1];
            qlo[kc][0] = ql[b0 + c0]; qlo[kc][1] = ql[b1 + c0];
            qlo[kc][2] = ql[b0 + c1]; qlo[kc][3] = ql[b1 + c1];
        }
    }

    float oacc[8][4];
    #pragma unroll
    for (int nb = 0; nb < 8; nb++)
        #pragma unroll
        for (int e = 0; e < 4; e++) oacc[nb][e] = 0.f;
    float m0 = -1e30f, m1 = -1e30f, l0 = 0.f, l1 = 0.f;

    const int wRowMax = qb * ABQ + w * 16 + 15;
    const int nKT = 2 * qb + 2;
    const size_t kbase = ((size_t)(b * NKV_ + kvh)) * S_ * 64;   // bf16 elems
    const size_t vbase = ((size_t)(b * NKV_ + kvh)) * 64 * S_;

    for (int kt = 0; kt < nKT; kt++) {
        // ---- cp.async tile loads (all threads) ----
        #pragma unroll
        for (int l = 0; l < 8; l++) {
            int idx = tid + l * 128;                  // 0..1023
            if (idx < 512) {                          // K: 32 rows x 8 chunks x 2
                int c = idx & 7, r = (idx >> 3) & 31, hl = idx >> 8;
                const __nv_bfloat16* src = (hl ? kl : kh) + kbase + (size_t)(kt * 32 + r) * 64 + c * 8;
                cp16(&sK[hl][r * 36 + c * 4], src);
            } else {                                  // V: 64 rows x 4 chunks x 2
                int j = idx - 512;
                int c = j & 3, d = (j >> 2) & 63, hl = j >> 8;
                const __nv_bfloat16* src = (hl ? vtl : vth) + vbase + (size_t)d * S_ + kt * 32 + c * 8;
                cp16(&sV[hl][d * 20 + c * 4], src);
            }
        }
        asm volatile("cp.async.commit_group;");
        asm volatile("cp.async.wait_group 0;");
        __syncthreads();

        if (kt * ABK <= wRowMax) {
            // ---- S = Q @ K^T (3 mma per n8 per k16) ----
            float sacc[4][4];
            #pragma unroll
            for (int nb = 0; nb < 4; nb++)
                #pragma unroll
                for (int e = 0; e < 4; e++) sacc[nb][e] = 0.f;

            #pragma unroll
            for (int kc = 0; kc < 4; kc++)
                #pragma unroll
                for (int nb = 0; nb < 4; nb++) {
                    int ko = (nb * 8 + g) * 36 + kc * 8 + tig;
                    uint32_t bh0 = sK[0][ko], bh1 = sK[0][ko + 4];
                    uint32_t bl0 = sK[1][ko], bl1 = sK[1][ko + 4];
                    mma_bf16(sacc[nb], qhi[kc], bl0, bl1);
                    mma_bf16(sacc[nb], qlo[kc], bh0, bh1);
                    mma_bf16(sacc[nb], qhi[kc], bh0, bh1);
                }

            // ---- causal mask + online softmax ----
            float mn0 = m0, mn1 = m1;
            #pragma unroll
            for (int nb = 0; nb < 4; nb++) {
                #pragma unroll
                for (int e = 0; e < 2; e++) {
                    int col = kt * ABK + nb * 8 + 2 * tig + e;
                    if (col > r0g) sacc[nb][e]     = -1e30f;
                    if (col > r1g) sacc[nb][e + 2] = -1e30f;
                    mn0 = fmaxf(mn0, sacc[nb][e]);
                    mn1 = fmaxf(mn1, sacc[nb][e + 2]);
                }
            }
            mn0 = fmaxf(mn0, __shfl_xor_sync(0xffffffffu, mn0, 1));
            mn0 = fmaxf(mn0, __shfl_xor_sync(0xffffffffu, mn0, 2));
            mn1 = fmaxf(mn1, __shfl_xor_sync(0xffffffffu, mn1, 1));
            mn1 = fmaxf(mn1, __shfl_xor_sync(0xffffffffu, mn1, 2));

            const float corr0 = __expf(m0 - mn0);
            const float corr1 = __expf(m1 - mn1);
            m0 = mn0; m1 = mn1;
            l0 *= corr0; l1 *= corr1;
            #pragma unroll
            for (int nb = 0; nb < 8; nb++) {
                oacc[nb][0] *= corr0; oacc[nb][1] *= corr0;
                oacc[nb][2] *= corr1; oacc[nb][3] *= corr1;
            }

            // probs in place of scores
            #pragma unroll
            for (int nb = 0; nb < 4; nb++) {
                sacc[nb][0] = __expf(sacc[nb][0] - mn0);
                sacc[nb][1] = __expf(sacc[nb][1] - mn0);
                sacc[nb][2] = __expf(sacc[nb][2] - mn1);
                sacc[nb][3] = __expf(sacc[nb][3] - mn1);
                l0 += sacc[nb][0] + sacc[nb][1];
                l1 += sacc[nb][2] + sacc[nb][3];
            }

            // ---- O += P @ V ; P A-frags by register repack of C-frags ----
            #pragma unroll
            for (int kc2 = 0; kc2 < 2; kc2++) {
                uint32_t phi[4], plo[4];
                split2(make_float2(sacc[2*kc2][0],     sacc[2*kc2][1]),     phi[0], plo[0]);
                split2(make_float2(sacc[2*kc2][2],     sacc[2*kc2][3]),     phi[1], plo[1]);
                split2(make_float2(sacc[2*kc2 + 1][0], sacc[2*kc2 + 1][1]), phi[2], plo[2]);
                split2(make_float2(sacc[2*kc2 + 1][2], sacc[2*kc2 + 1][3]), phi[3], plo[3]);
                #pragma unroll
                for (int nb = 0; nb < 8; nb++) {
                    int vo = (nb * 8 + g) * 20 + kc2 * 8 + tig;
                    uint32_t bh0 = sV[0][vo], bh1 = sV[0][vo + 4];
                    uint32_t bl0 = sV[1][vo], bl1 = sV[1][vo + 4];
                    mma_bf16(oacc[nb], phi, bl0, bl1);
                    mma_bf16(oacc[nb], plo, bh0, bh1);
                    mma_bf16(oacc[nb], phi, bh0, bh1);
                }
            }
        }
        __syncthreads();
    }

    // ---- epilogue: normalize, split to bf16 hi/lo, store ----
    l0 += __shfl_xor_sync(0xffffffffu, l0, 1);
    l0 += __shfl_xor_sync(0xffffffffu, l0, 2);
    l1 += __shfl_xor_sync(0xffffffffu, l1, 1);
    l1 += __shfl_xor_sync(0xffffffffu, l1, 2);
    const float inv0 = 1.f / l0;
    const float inv1 = 1.f / l1;

    const size_t o0 = (((size_t)(b * S_ + r0g)) * 1024 + h * 64) >> 1;
    const size_t o1 = (((size_t)(b * S_ + r1g)) * 1024 + h * 64) >> 1;
    #pragma unroll
    for (int nb = 0; nb < 8; nb++) {
        uint32_t hi, lo;
        size_t c = nb * 4 + tig;
        split2(make_float2(oacc[nb][0] * inv0, oacc[nb][1] * inv0), hi, lo);
        oh[o0 + c] = hi; ol[o0 + c] = lo;
        split2(make_float2(oacc[nb][2] * inv1, oacc[nb][3] * inv1), hi, lo);
        oh[o1 + c] = hi; ol[o1 + c] = lo;
    }
}

// ---------------------------------------------------------------------------
// Launch. Inputs: 0 query, 1 key, 2 value, 3 attn_mask, 4 Wq, 5 Wk, 6 Wv, 7 Wo
// ---------------------------------------------------------------------------
extern "C" void kernel_launch(void* const* d_in, const int* in_sizes, int n_in,
                              void* d_out, int out_size)
{
    const float* query = (const float*)d_in[0];
    const float* key   = (const float*)d_in[1];
    const float* value = (const float*)d_in[2];
    const float* Wq    = (const float*)d_in[4];
    const float* Wk    = (const float*)d_in[5];
    const float* Wv    = (const float*)d_in[6];
    const float* Wo    = (const float*)d_in[7];
    float* out = (float*)d_out;

    float *q, *k, *v;
    cudaGetSymbolAddress((void**)&q, g_q);
    cudaGetSymbolAddress((void**)&k, g_k);
    cudaGetSymbolAddress((void**)&v, g_v);
    __nv_bfloat16 *qxh, *qxl, *kxh, *kxl, *vxh, *vxl, *wqh, *wql, *wkh, *wkl, *wvh, *wvl, *woh, *wol;
    __nv_bfloat16 *qah, *qal, *kah, *kal, *vth, *vtl, *ah, *al;
    cudaGetSymbolAddress((void**)&qxh, g_qxh); cudaGetSymbolAddress((void**)&qxl, g_qxl);
    cudaGetSymbolAddress((void**)&kxh, g_kxh); cudaGetSymbolAddress((void**)&kxl, g_kxl);
    cudaGetSymbolAddress((void**)&vxh, g_vxh); cudaGetSymbolAddress((void**)&vxl, g_vxl);
    cudaGetSymbolAddress((void**)&wqh, g_wqh); cudaGetSymbolAddress((void**)&wql, g_wql);
    cudaGetSymbolAddress((void**)&wkh, g_wkh); cudaGetSymbolAddress((void**)&wkl, g_wkl);
    cudaGetSymbolAddress((void**)&wvh, g_wvh); cudaGetSymbolAddress((void**)&wvl, g_wvl);
    cudaGetSymbolAddress((void**)&woh, g_woh); cudaGetSymbolAddress((void**)&wol, g_wol);
    cudaGetSymbolAddress((void**)&qah, g_qah); cudaGetSymbolAddress((void**)&qal, g_qal);
    cudaGetSymbolAddress((void**)&kah, g_kah); cudaGetSymbolAddress((void**)&kal, g_kal);
    cudaGetSymbolAddress((void**)&vth, g_vth); cudaGetSymbolAddress((void**)&vtl, g_vtl);
    cudaGetSymbolAddress((void**)&ah,  g_ah);  cudaGetSymbolAddress((void**)&al,  g_al);

    // ---- split GEMM inputs ----
    split_kernel<<<4096, 256>>>((const float4*)query, (uint2*)qxh, (uint2*)qxl, MTOT*1024/4);
    split_kernel<<<4096, 256>>>((const float4*)key,   (uint2*)kxh, (uint2*)kxl, MTOT*1024/4);
    split_kernel<<<4096, 256>>>((const float4*)value, (uint2*)vxh, (uint2*)vxl, MTOT*1024/4);
    split_kernel<<<1024, 256>>>((const float4*)Wq, (uint2*)wqh, (uint2*)wql, 1024*1024/4);
    split_kernel<<< 256, 256>>>((const float4*)Wk, (uint2*)wkh, (uint2*)wkl, 256*1024/4);
    split_kernel<<< 256, 256>>>((const float4*)Wv, (uint2*)wvh, (uint2*)wvl, 256*1024/4);
    split_kernel<<<1024, 256>>>((const float4*)Wo, (uint2*)woh, (uint2*)wol, 1024*1024/4);

    // ---- projections ----
    gemm_bf16_kernel<<<dim3(8, 32), 256>>>(qxh, qxl, wqh, wql, q, MTOT, 1024, 1024);
    gemm_bf16_kernel<<<dim3(2, 32), 256>>>(kxh, kxl, wkh, wkl, k, MTOT, 256, 1024);
    gemm_bf16_kernel<<<dim3(2, 32), 256>>>(vxh, vxl, wvh, wvl, v, MTOT, 256, 1024);

    // ---- convert attention operands ----
    conv_q_kernel<<<4096, 256>>>((const float4*)q, (uint2*)qah, (uint2*)qal, MTOT*1024/4);
    conv_k_kernel<<<1024, 256>>>((const float4*)k, (uint2*)kah, (uint2*)kal);
    conv_vt_kernel<<<dim3(S_/32, HD_/32, B_*NKV_), dim3(32, 8)>>>(v, vth, vtl);

    // ---- attention ----
    attn_mma_kernel<<<dim3(S_/ABQ, NH_, B_), 128>>>(
        (const uint32_t*)qah, (const uint32_t*)qal, kah, kal, vth, vtl,
        (uint32_t*)ah, (uint32_t*)al);

    // ---- output projection ----
    gemm_bf16_kernel<<<dim3(8, 32), 256>>>(ah, al, woh, wol, out, MTOT, 1024, 1024);
}

// round 9
// speedup vs baseline: 1.7166x; 1.7166x over previous
#include <cuda_runtime.h>
#include <cuda_bf16.h>
#include <mma.h>
#include <cstdint>

using namespace nvcuda;

// Problem constants
#define B_  2
#define S_  2048
#define E_  1024
#define NH_ 16
#define NKV_ 4
#define HD_ 64
#define GS_ 4
#define MTOT (B_*S_)    // 4096

// ---------------- scratch ----------------
__device__ __align__(16) float g_q[MTOT * 1024];
__device__ __align__(16) float g_k[MTOT * 256];
__device__ __align__(16) float g_v[MTOT * 256];
__device__ __align__(16) float g_attn[MTOT * 1024];
// attention operands (pre-split bf16)
__device__ __align__(16) __nv_bfloat16 g_qah[MTOT*1024], g_qal[MTOT*1024];           // Q scaled
__device__ __align__(16) __nv_bfloat16 g_kah[B_*NKV_*S_*HD_], g_kal[B_*NKV_*S_*HD_]; // [b][kvh][s][d]
__device__ __align__(16) __nv_bfloat16 g_vth[B_*NKV_*S_*HD_], g_vtl[B_*NKV_*S_*HD_]; // [b][kvh][d][s]

// ---------------- helpers ----------------
__device__ __forceinline__ uint32_t pack2(float x, float y) {
    __nv_bfloat162 t = __floats2bfloat162_rn(x, y);
    return *(uint32_t*)&t;
}
__device__ __forceinline__ float bf16hi(float x) {
    return __bfloat162float(__float2bfloat16_rn(x));
}
__device__ __forceinline__ void split2(float2 v, uint32_t& hi, uint32_t& lo) {
    float hx = bf16hi(v.x), hy = bf16hi(v.y);
    hi = pack2(hx, hy);
    lo = pack2(v.x - hx, v.y - hy);
}
__device__ __forceinline__ void mma_bf16(float c[4], const uint32_t a[4],
                                         uint32_t b0, uint32_t b1)
{
    asm volatile(
        "mma.sync.aligned.m16n8k16.row.col.f32.bf16.bf16.f32 "
        "{%0,%1,%2,%3}, {%4,%5,%6,%7}, {%8,%9}, {%0,%1,%2,%3};"
        : "+f"(c[0]), "+f"(c[1]), "+f"(c[2]), "+f"(c[3])
        : "r"(a[0]), "r"(a[1]), "r"(a[2]), "r"(a[3]), "r"(b0), "r"(b1));
}
__device__ __forceinline__ void cp16(void* smem_dst, const void* gsrc) {
    uint32_t d = (uint32_t)__cvta_generic_to_shared(smem_dst);
    asm volatile("cp.async.cg.shared.global [%0], [%1], 16;" :: "r"(d), "l"(gsrc));
}
__device__ __forceinline__ void ldm4(uint32_t r[4], uint32_t addr) {
    asm volatile("ldmatrix.sync.aligned.m8n8.x4.shared.b16 {%0,%1,%2,%3}, [%4];"
        : "=r"(r[0]), "=r"(r[1]), "=r"(r[2]), "=r"(r[3]) : "r"(addr));
}

// ---------------- conversion kernels ----------------
// Q for attention: scale by 0.125 then split
__global__ void conv_q_kernel(const float4* __restrict__ in,
                              uint2* __restrict__ hi, uint2* __restrict__ lo, int n4)
{
    int i = blockIdx.x * blockDim.x + threadIdx.x;
    if (i >= n4) return;
    float4 v = in[i];
    v.x *= 0.125f; v.y *= 0.125f; v.z *= 0.125f; v.w *= 0.125f;
    uint32_t h0, l0, h1, l1;
    split2(make_float2(v.x, v.y), h0, l0);
    split2(make_float2(v.z, v.w), h1, l1);
    hi[i] = make_uint2(h0, h1);
    lo[i] = make_uint2(l0, l1);
}

// K: [b][s][kvh*64+d] f32 -> [b][kvh][s][d] bf16 hi/lo
__global__ void conv_k_kernel(const float4* __restrict__ in,
                              uint2* __restrict__ hi, uint2* __restrict__ lo)
{
    int i = blockIdx.x * blockDim.x + threadIdx.x;  // MTOT*256/4 = 262144
    int c4 = i & 63;
    int s  = (i >> 6) & 2047;
    int b  = i >> 17;
    int kvh = c4 >> 4, d4 = c4 & 15;
    float4 v = in[i];
    uint32_t h0, l0, h1, l1;
    split2(make_float2(v.x, v.y), h0, l0);
    split2(make_float2(v.z, v.w), h1, l1);
    int o = ((b * 4 + kvh) * 2048 + s) * 16 + d4;
    hi[o] = make_uint2(h0, h1);
    lo[o] = make_uint2(l0, l1);
}

// V: [b][s][kvh*64+d] f32 -> transposed [b][kvh][d][s] bf16 hi/lo
__global__ void conv_vt_kernel(const float* __restrict__ V,
                               __nv_bfloat16* __restrict__ vth,
                               __nv_bfloat16* __restrict__ vtl)
{
    __shared__ float ts[32][33];
    const int s0 = blockIdx.x * 32, d0 = blockIdx.y * 32;
    const int bh = blockIdx.z;
    const int b = bh >> 2, kvh = bh & 3;
    const int x = threadIdx.x, y = threadIdx.y;

    #pragma unroll
    for (int l = 0; l < 4; l++) {
        int s = s0 + y + l * 8;
        ts[y + l * 8][x] = V[((size_t)(b * 2048 + s)) * 256 + kvh * 64 + d0 + x];
    }
    __syncthreads();
    #pragma unroll
    for (int l = 0; l < 4; l++) {
        int d = d0 + y + l * 8;
        float f = ts[x][y + l * 8];
        float h = bf16hi(f);
        size_t o = ((size_t)(bh * 64 + d)) * 2048 + s0 + x;
        vth[o] = __float2bfloat16_rn(h);
        vtl[o] = __float2bfloat16_rn(f - h);
    }
}

// ---------------------------------------------------------------------------
// tf32 GEMM, 3-stage cp.async pipeline: C[M,N] = X[M,K] @ W[N,K]^T
// Block 128x128, BK=16, 8 warps (warp 64x32), wmma 16x16x8 tf32.
// Dynamic smem: Xs[3][128][20] | Ws[3][128][20]  (61440 B)
// ---------------------------------------------------------------------------
#define GBK 16
#define GPAD 20
#define GSTAGE_F (128 * GPAD)       // floats per stage per matrix

__device__ __forceinline__ void gemm_body(const float* __restrict__ X,
                                          const float* __restrict__ W,
                                          float* __restrict__ C,
                                          int M, int N, int K, float* sm)
{
    float* Xs = sm;                   // 3 stages
    float* Ws = sm + 3 * GSTAGE_F;

    const int tid = threadIdx.x;
    const int wid = tid >> 5;
    const int wr  = wid & 1;
    const int wc  = wid >> 1;
    const int m0  = blockIdx.y * 128;
    const int n0  = blockIdx.x * 128;

    wmma::fragment<wmma::accumulator, 16, 16, 8, float> acc[4][2];
    #pragma unroll
    for (int i = 0; i < 4; i++)
        #pragma unroll
        for (int j = 0; j < 2; j++)
            wmma::fill_fragment(acc[i][j], 0.0f);

    auto prefetch = [&](int kt, int st) {
        const int k0 = kt * GBK;
        float* xs = Xs + st * GSTAGE_F;
        float* ws = Ws + st * GSTAGE_F;
        #pragma unroll
        for (int l = 0; l < 2; l++) {
            int idx = tid + l * 256;       // 0..511
            int r   = idx >> 2;            // 0..127
            int c4  = idx & 3;             // 0..3
            cp16(&xs[r * GPAD + c4 * 4], &X[(size_t)(m0 + r) * K + k0 + c4 * 4]);
            cp16(&ws[r * GPAD + c4 * 4], &W[(size_t)(n0 + r) * K + k0 + c4 * 4]);
        }
        asm volatile("cp.async.commit_group;");
    };

    const int nKT = K / GBK;
    prefetch(0, 0);
    if (nKT > 1) prefetch(1, 1);

    int pst = 2 % 3;
    for (int kt = 0; kt < nKT; kt++) {
        asm volatile("cp.async.wait_group 1;");
        __syncthreads();
        if (kt + 2 < nKT) {
            prefetch(kt + 2, pst);
            pst = (pst + 1 == 3) ? 0 : pst + 1;
        } else {
            asm volatile("cp.async.commit_group;");   // keep group count in sync
        }
        const int st = kt % 3;
        const float* xs = Xs + st * GSTAGE_F;
        const float* ws = Ws + st * GSTAGE_F;

        #pragma unroll
        for (int ks = 0; ks < GBK; ks += 8) {
            wmma::fragment<wmma::matrix_a, 16, 16, 8, wmma::precision::tf32, wmma::row_major> a[4];
            wmma::fragment<wmma::matrix_b, 16, 16, 8, wmma::precision::tf32, wmma::col_major> bfr[2];
            #pragma unroll
            for (int i = 0; i < 4; i++) {
                wmma::load_matrix_sync(a[i], &xs[(wr * 64 + i * 16) * GPAD + ks], GPAD);
                #pragma unroll
                for (int t = 0; t < a[i].num_elements; t++)
                    a[i].x[t] = wmma::__float_to_tf32(a[i].x[t]);
            }
            #pragma unroll
            for (int j = 0; j < 2; j++) {
                wmma::load_matrix_sync(bfr[j], &ws[(wc * 32 + j * 16) * GPAD + ks], GPAD);
                #pragma unroll
                for (int t = 0; t < bfr[j].num_elements; t++)
                    bfr[j].x[t] = wmma::__float_to_tf32(bfr[j].x[t]);
            }
            #pragma unroll
            for (int i = 0; i < 4; i++)
                #pragma unroll
                for (int j = 0; j < 2; j++)
                    wmma::mma_sync(acc[i][j], a[i], bfr[j], acc[i][j]);
        }
    }

    #pragma unroll
    for (int i = 0; i < 4; i++)
        #pragma unroll
        for (int j = 0; j < 2; j++)
            wmma::store_matrix_sync(&C[(size_t)(m0 + wr * 64 + i * 16) * N + n0 + wc * 32 + j * 16],
                                    acc[i][j], N, wmma::mem_row_major);
}

__global__ __launch_bounds__(256, 2)
void gemm_q_kernel(const float* __restrict__ X, const float* __restrict__ W,
                   float* __restrict__ C, int M, int N, int K)
{
    extern __shared__ float sm[];
    gemm_body(X, W, C, M, N, K, sm);
}

__global__ __launch_bounds__(256, 2)
void gemm_kv_kernel(const float* __restrict__ X0, const float* __restrict__ W0, float* __restrict__ C0,
                    const float* __restrict__ X1, const float* __restrict__ W1, float* __restrict__ C1,
                    int M, int N, int K)
{
    extern __shared__ float sm[];
    if (blockIdx.z == 0) gemm_body(X0, W0, C0, M, N, K, sm);
    else                 gemm_body(X1, W1, C1, M, N, K, sm);
}

// ---------------------------------------------------------------------------
// Flash attention, bf16 hi/lo split mma.m16n8k16, ldmatrix b-fragment feeds.
// CTA 128 thr / 4 warps, BQ=64, BK=32. Writes f32 output.
// ---------------------------------------------------------------------------
#define ABQ 64
#define ABK 32

__global__ __launch_bounds__(128, 4)
void attn_mma_kernel(const uint32_t* __restrict__ qh, const uint32_t* __restrict__ ql,
                     const __nv_bfloat16* __restrict__ kh, const __nv_bfloat16* __restrict__ kl,
                     const __nv_bfloat16* __restrict__ vth, const __nv_bfloat16* __restrict__ vtl,
                     float* __restrict__ O)
{
    __shared__ __align__(16) uint32_t sK[2][32 * 36];   // [hi/lo][key][d-pair] stride 36
    __shared__ __align__(16) uint32_t sV[2][64 * 20];   // [hi/lo][d][key-pair] stride 20

    const int qb   = gridDim.x - 1 - blockIdx.x;
    const int h    = blockIdx.y;
    const int b    = blockIdx.z;
    const int kvh  = h >> 2;
    const int tid  = threadIdx.x;
    const int lane = tid & 31;
    const int w    = tid >> 5;
    const int g    = lane >> 2;
    const int tig  = lane & 3;

    const int r0g = qb * ABQ + w * 16 + g;
    const int r1g = r0g + 8;

    // ldmatrix per-lane address components
    const int sel  = lane >> 3;          // 0..3 (matrix id)
    const int rowm = lane & 7;
    const int kofsB = ((((sel >> 1) * 8 + rowm) * 36) + (sel & 1) * 4) * 4;  // bytes
    const int vofsB = ((((sel >> 1) * 8 + rowm) * 20) + (sel & 1) * 4) * 4;
    const uint32_t sKhiA = (uint32_t)__cvta_generic_to_shared(&sK[0][0]);
    const uint32_t sKloA = (uint32_t)__cvta_generic_to_shared(&sK[1][0]);
    const uint32_t sVhiA = (uint32_t)__cvta_generic_to_shared(&sV[0][0]);
    const uint32_t sVloA = (uint32_t)__cvta_generic_to_shared(&sV[1][0]);

    // ---- Q A-fragments from global (one-time) ----
    uint32_t qhi[4][4], qlo[4][4];
    {
        const size_t b0 = (((size_t)(b * S_ + r0g)) * 1024 + h * 64) >> 1;
        const size_t b1 = (((size_t)(b * S_ + r1g)) * 1024 + h * 64) >> 1;
        #pragma unroll
        for (int kc = 0; kc < 4; kc++) {
            int c0 = kc * 8 + tig, c1 = c0 + 4;
            qhi[kc][0] = qh[b0 + c0]; qhi[kc][1] = qh[b1 + c0];
            qhi[kc][2] = qh[b0 + c1]; qhi[kc][3] = qh[b1 + c1];
            qlo[kc][0] = ql[b0 + c0]; qlo[kc][1] = ql[b1 + c0];
            qlo[kc][2] = ql[b0 + c1]; qlo[kc][3] = ql[b1 + c1];
        }
    }

    float oacc[8][4];
    #pragma unroll
    for (int nb = 0; nb < 8; nb++)
        #pragma unroll
        for (int e = 0; e < 4; e++) oacc[nb][e] = 0.f;
    float m0 = -1e30f, m1 = -1e30f, l0 = 0.f, l1 = 0.f;

    const int wRowMax = qb * ABQ + w * 16 + 15;
    const int nKT = 2 * qb + 2;
    const size_t kbase = ((size_t)(b * NKV_ + kvh)) * S_ * 64;
    const size_t vbase = ((size_t)(b * NKV_ + kvh)) * 64 * S_;

    for (int kt = 0; kt < nKT; kt++) {
        // ---- cp.async tile loads ----
        #pragma unroll
        for (int l = 0; l < 8; l++) {
            int idx = tid + l * 128;                  // 0..1023
            if (idx < 512) {                          // K
                int c = idx & 7, r = (idx >> 3) & 31, hl = idx >> 8;
                const __nv_bfloat16* src = (hl ? kl : kh) + kbase + (size_t)(kt * 32 + r) * 64 + c * 8;
                cp16(&sK[hl][r * 36 + c * 4], src);
            } else {                                  // V
                int j = idx - 512;
                int c = j & 3, d = (j >> 2) & 63, hl = j >> 8;
                const __nv_bfloat16* src = (hl ? vtl : vth) + vbase + (size_t)d * S_ + kt * 32 + c * 8;
                cp16(&sV[hl][d * 20 + c * 4], src);
            }
        }
        asm volatile("cp.async.commit_group;");
        asm volatile("cp.async.wait_group 0;");
        __syncthreads();

        if (kt * ABK <= wRowMax) {
            // ---- S = Q @ K^T ----
            float sacc[4][4];
            #pragma unroll
            for (int nb = 0; nb < 4; nb++)
                #pragma unroll
                for (int e = 0; e < 4; e++) sacc[nb][e] = 0.f;

            #pragma unroll
            for (int kc = 0; kc < 4; kc++) {
                #pragma unroll
                for (int nbp = 0; nbp < 2; nbp++) {
                    uint32_t off = (uint32_t)((nbp * 16 * 36 + kc * 8) * 4) + kofsB;
                    uint32_t H[4], L[4];
                    ldm4(H, sKhiA + off);
                    ldm4(L, sKloA + off);
                    mma_bf16(sacc[2*nbp],   qhi[kc], L[0], L[1]);
                    mma_bf16(sacc[2*nbp],   qlo[kc], H[0], H[1]);
                    mma_bf16(sacc[2*nbp],   qhi[kc], H[0], H[1]);
                    mma_bf16(sacc[2*nbp+1], qhi[kc], L[2], L[3]);
                    mma_bf16(sacc[2*nbp+1], qlo[kc], H[2], H[3]);
                    mma_bf16(sacc[2*nbp+1], qhi[kc], H[2], H[3]);
                }
            }

            // ---- causal mask + online softmax ----
            float mn0 = m0, mn1 = m1;
            #pragma unroll
            for (int nb = 0; nb < 4; nb++) {
                #pragma unroll
                for (int e = 0; e < 2; e++) {
                    int col = kt * ABK + nb * 8 + 2 * tig + e;
                    if (col > r0g) sacc[nb][e]     = -1e30f;
                    if (col > r1g) sacc[nb][e + 2] = -1e30f;
                    mn0 = fmaxf(mn0, sacc[nb][e]);
                    mn1 = fmaxf(mn1, sacc[nb][e + 2]);
                }
            }
            mn0 = fmaxf(mn0, __shfl_xor_sync(0xffffffffu, mn0, 1));
            mn0 = fmaxf(mn0, __shfl_xor_sync(0xffffffffu, mn0, 2));
            mn1 = fmaxf(mn1, __shfl_xor_sync(0xffffffffu, mn1, 1));
            mn1 = fmaxf(mn1, __shfl_xor_sync(0xffffffffu, mn1, 2));

            const float corr0 = __expf(m0 - mn0);
            const float corr1 = __expf(m1 - mn1);
            m0 = mn0; m1 = mn1;
            l0 *= corr0; l1 *= corr1;
            #pragma unroll
            for (int nb = 0; nb < 8; nb++) {
                oacc[nb][0] *= corr0; oacc[nb][1] *= corr0;
                oacc[nb][2] *= corr1; oacc[nb][3] *= corr1;
            }

            #pragma unroll
            for (int nb = 0; nb < 4; nb++) {
                sacc[nb][0] = __expf(sacc[nb][0] - mn0);
                sacc[nb][1] = __expf(sacc[nb][1] - mn0);
                sacc[nb][2] = __expf(sacc[nb][2] - mn1);
                sacc[nb][3] = __expf(sacc[nb][3] - mn1);
                l0 += sacc[nb][0] + sacc[nb][1];
                l1 += sacc[nb][2] + sacc[nb][3];
            }

            // ---- O += P @ V (P A-frags by register repack) ----
            #pragma unroll
            for (int kc2 = 0; kc2 < 2; kc2++) {
                uint32_t phi[4], plo[4];
                split2(make_float2(sacc[2*kc2][0],     sacc[2*kc2][1]),     phi[0], plo[0]);
                split2(make_float2(sacc[2*kc2][2],     sacc[2*kc2][3]),     phi[1], plo[1]);
                split2(make_float2(sacc[2*kc2 + 1][0], sacc[2*kc2 + 1][1]), phi[2], plo[2]);
                split2(make_float2(sacc[2*kc2 + 1][2], sacc[2*kc2 + 1][3]), phi[3], plo[3]);
                #pragma unroll
                for (int nbp = 0; nbp < 4; nbp++) {
                    uint32_t off = (uint32_t)((nbp * 16 * 20 + kc2 * 8) * 4) + vofsB;
                    uint32_t H[4], L[4];
                    ldm4(H, sVhiA + off);
                    ldm4(L, sVloA + off);
                    mma_bf16(oacc[2*nbp],   phi, L[0], L[1]);
                    mma_bf16(oacc[2*nbp],   plo, H[0], H[1]);
                    mma_bf16(oacc[2*nbp],   phi, H[0], H[1]);
                    mma_bf16(oacc[2*nbp+1], phi, L[2], L[3]);
                    mma_bf16(oacc[2*nbp+1], plo, H[2], H[3]);
                    mma_bf16(oacc[2*nbp+1], phi, H[2], H[3]);
                }
            }
        }
        __syncthreads();
    }

    // ---- epilogue ----
    l0 += __shfl_xor_sync(0xffffffffu, l0, 1);
    l0 += __shfl_xor_sync(0xffffffffu, l0, 2);
    l1 += __shfl_xor_sync(0xffffffffu, l1, 1);
    l1 += __shfl_xor_sync(0xffffffffu, l1, 2);
    const float inv0 = 1.f / l0;
    const float inv1 = 1.f / l1;

    float* op0 = O + ((size_t)(b * S_ + r0g)) * 1024 + h * 64;
    float* op1 = O + ((size_t)(b * S_ + r1g)) * 1024 + h * 64;
    #pragma unroll
    for (int nb = 0; nb < 8; nb++) {
        *(float2*)&op0[nb * 8 + 2 * tig] = make_float2(oacc[nb][0] * inv0, oacc[nb][1] * inv0);
        *(float2*)&op1[nb * 8 + 2 * tig] = make_float2(oacc[nb][2] * inv1, oacc[nb][3] * inv1);
    }
}

// ---------------------------------------------------------------------------
// Launch. Inputs: 0 query, 1 key, 2 value, 3 attn_mask, 4 Wq, 5 Wk, 6 Wv, 7 Wo
// ---------------------------------------------------------------------------
extern "C" void kernel_launch(void* const* d_in, const int* in_sizes, int n_in,
                              void* d_out, int out_size)
{
    const float* query = (const float*)d_in[0];
    const float* key   = (const float*)d_in[1];
    const float* value = (const float*)d_in[2];
    const float* Wq    = (const float*)d_in[4];
    const float* Wk    = (const float*)d_in[5];
    const float* Wv    = (const float*)d_in[6];
    const float* Wo    = (const float*)d_in[7];
    float* out = (float*)d_out;

    float *q, *k, *v, *attn;
    cudaGetSymbolAddress((void**)&q,    g_q);
    cudaGetSymbolAddress((void**)&k,    g_k);
    cudaGetSymbolAddress((void**)&v,    g_v);
    cudaGetSymbolAddress((void**)&attn, g_attn);
    __nv_bfloat16 *qah, *qal, *kah, *kal, *vth, *vtl;
    cudaGetSymbolAddress((void**)&qah, g_qah); cudaGetSymbolAddress((void**)&qal, g_qal);
    cudaGetSymbolAddress((void**)&kah, g_kah); cudaGetSymbolAddress((void**)&kal, g_kal);
    cudaGetSymbolAddress((void**)&vth, g_vth); cudaGetSymbolAddress((void**)&vtl, g_vtl);

    const int dynsmem = 6 * GSTAGE_F * 4;   // 61440 B
    cudaFuncSetAttribute(gemm_q_kernel,  cudaFuncAttributeMaxDynamicSharedMemorySize, dynsmem);
    cudaFuncSetAttribute(gemm_kv_kernel, cudaFuncAttributeMaxDynamicSharedMemorySize, dynsmem);

    // ---- projections (tf32) ----
    gemm_q_kernel<<<dim3(8, 32), 256, dynsmem>>>(query, Wq, q, MTOT, 1024, 1024);
    gemm_kv_kernel<<<dim3(2, 32, 2), 256, dynsmem>>>(key, Wk, k, value, Wv, v, MTOT, 256, 1024);

    // ---- convert attention operands ----
    conv_q_kernel<<<4096, 256>>>((const float4*)q, (uint2*)qah, (uint2*)qal, MTOT*1024/4);
    conv_k_kernel<<<1024, 256>>>((const float4*)k, (uint2*)kah, (uint2*)kal);
    conv_vt_kernel<<<dim3(S_/32, HD_/32, B_*NKV_), dim3(32, 8)>>>(v, vth, vtl);

    // ---- attention ----
    attn_mma_kernel<<<dim3(S_/ABQ, NH_, B_), 128>>>(
        (const uint32_t*)qah, (const uint32_t*)qal, kah, kal, vth, vtl, attn);

    // ---- output projection (tf32) ----
    gemm_q_kernel<<<dim3(8, 32), 256, dynsmem>>>(attn, Wo, out, MTOT, 1024, 1024);
}